// round 16
// baseline (speedup 1.0000x reference)
#include <cuda_runtime.h>
#include <cstdint>
#include <cstddef>

// out[n, l, o] = weight[o, l]   for n in [0,128), l,o in [0,1024)
// 512 MB broadcast-write of weight.T.
// Round 16: warp-SHUFFLE transpose — removes smem (STS+LDS L1 wavefronts)
// and the block barrier from the prologue, testing whether L1tex (76-82%)
// is co-limiting the 82% DRAM duty. Store side identical to the R8 optimum:
// 32768 blocks, 256 thr, 4 __stcs STG.128/thread, 4x128B warp segments.
//
// Warp tile: input  32(o) x 4(l)  — lane loads w[o_warp+lane][l0..l0+3]
//            output  4(l) x 32(o) — lane (l_idx=lane>>3, c=lane&7) holds
//                                   float4 w[o_warp+c*4 .. +3][l0+l_idx]

namespace {
constexpr int L   = 1024;
constexpr int OUT = 1024;
constexpr int N   = 128;

constexpr int NZ = 32;                 // plane split
constexpr int N_PER_BLOCK = N / NZ;    // 4 planes per block
constexpr int THREADS = 256;           // 8 warps
// grid: x = L/4 = 256 l-chunks, y = OUT/256 = 4 o-chunks, z = 32
}

__global__ __launch_bounds__(THREADS)
void linfwddiff_shfl(const float* __restrict__ w,
                     float* __restrict__ out) {
    const int lane = threadIdx.x & 31;
    const int warp = threadIdx.x >> 5;

    const int l0     = blockIdx.x * 4;                 // 4 l-values per block
    const int o_warp = blockIdx.y * 256 + warp * 32;   // 32 o-values per warp
    const int n0     = blockIdx.z * N_PER_BLOCK;

    // ---- Coalesced load: lane -> row o_warp+lane, float4 of l-values ----
    const float4 v = *reinterpret_cast<const float4*>(
        &w[(size_t)(o_warp + lane) * L + l0]);

    // ---- Warp shuffle transpose ----
    const int l_idx = lane >> 3;       // 0..3  (output l-row within chunk)
    const int c     = lane & 7;        // 0..7  (output o float4 column)
    const unsigned m = 0xffffffffu;

    float comp[4];
#pragma unroll
    for (int i = 0; i < 4; i++) {
        const int src = c * 4 + i;     // source lane holding row o_warp+c*4+i
        const float t0 = __shfl_sync(m, v.x, src);
        const float t1 = __shfl_sync(m, v.y, src);
        const float t2 = __shfl_sync(m, v.z, src);
        const float t3 = __shfl_sync(m, v.w, src);
        comp[i] = (l_idx == 0) ? t0 : (l_idx == 1) ? t1 : (l_idx == 2) ? t2 : t3;
    }
    const float4 va = make_float4(comp[0], comp[1], comp[2], comp[3]);

    // ---- Replicate-store across n: pure STG.128 stream, evict-first ----
    const size_t plane = (size_t)L * OUT;
    const size_t offa  = (size_t)(l0 + l_idx) * OUT + o_warp + c * 4;
    size_t base = (size_t)n0 * plane;

#pragma unroll
    for (int n = 0; n < N_PER_BLOCK; n++) {
        __stcs(reinterpret_cast<float4*>(&out[base + offa]), va);
        base += plane;
    }
}

extern "C" void kernel_launch(void* const* d_in, const int* in_sizes, int n_in,
                              void* d_out, int out_size) {
    // d_in[0] = x (unused — reference discards net(x)), d_in[1] = weight [1024,1024]
    const float* weight = (const float*)d_in[1];
    float* out = (float*)d_out;

    dim3 grid(L / 4, OUT / 256, NZ);   // (256, 4, 32) = 32768 blocks
    linfwddiff_shfl<<<grid, THREADS>>>(weight, out);
}